// round 8
// baseline (speedup 1.0000x reference)
#include <cuda_runtime.h>
#include <cuda_fp8.h>
#include <cuda_bf16.h>

#define S_N     32
#define NHEAD   32
#define HDIM    128
#define NKVH    8
#define GQ      4
#define BSZ     16
#define MBLK    128
#define NSPLIT  16
#define CHUNK   128
#define TILE    32
#define ROWB    136          // bf16 elems per K smem row (272B: conflict-free)
#define ROWF    132          // f32 elems per V smem row (528B: conflict-free)
#define ATTN_SCALE 0.08838834764831845f
#define NEG_BIG   -3.402823466e38f

// split-KV partial scratch (static device memory: allocation-free)
__device__ float g_po[S_N][NKVH][NSPLIT][GQ][HDIM];
__device__ float g_pm[S_N][NKVH][NSPLIT][GQ];
__device__ float g_pl[S_N][NKVH][NSPLIT][GQ];
__device__ int   g_cnt[S_N][NKVH];   // zero-init; protocol restores 0 every run

// Exact emulation of reference dequant chain -> two packed bf16x2 words
__device__ __forceinline__ uint2 dq4_bf(float4 c, float s) {
    float2 a = make_float2(c.x, c.y);
    float2 b = make_float2(c.z, c.w);
    __nv_fp8x2_storage_t p0 = __nv_cvt_float2_to_fp8x2(a, __NV_SATFINITE, __NV_E4M3);
    __nv_fp8x2_storage_t p1 = __nv_cvt_float2_to_fp8x2(b, __NV_SATFINITE, __NV_E4M3);
    __half2_raw h0 = __nv_cvt_fp8x2_to_halfraw2(p0, __NV_E4M3);
    __half2_raw h1 = __nv_cvt_fp8x2_to_halfraw2(p1, __NV_E4M3);
    float2 f0 = __half22float2(*reinterpret_cast<__half2*>(&h0));
    float2 f1 = __half22float2(*reinterpret_cast<__half2*>(&h1));
    f0.x *= s; f0.y *= s; f1.x *= s; f1.y *= s;
    __nv_bfloat162 bb0 = __float22bfloat162_rn(f0);
    __nv_bfloat162 bb1 = __float22bfloat162_rn(f1);
    uint2 r;
    r.x = *reinterpret_cast<unsigned*>(&bb0);
    r.y = *reinterpret_cast<unsigned*>(&bb1);
    return r;
}

// Same chain widened to f32 (exact bf16 values) — for the V tile
__device__ __forceinline__ float4 dq4_f32(float4 c, float s) {
    uint2 u = dq4_bf(c, s);
    float4 r;
    r.x = __uint_as_float(u.x << 16);
    r.y = __uint_as_float(u.x & 0xFFFF0000u);
    r.z = __uint_as_float(u.y << 16);
    r.w = __uint_as_float(u.y & 0xFFFF0000u);
    return r;
}

// bf16x2 word -> two exact f32 (bf16 value = upper 16 bits of f32)
__device__ __forceinline__ float bflo(unsigned u) { return __uint_as_float(u << 16); }
__device__ __forceinline__ float bfhi(unsigned u) { return __uint_as_float(u & 0xFFFF0000u); }

__global__ void __launch_bounds__(128)
attn_fused_kernel(const float* __restrict__ q, const float* __restrict__ knew,
                  const float* __restrict__ vnew, const float* __restrict__ kcache,
                  const float* __restrict__ vcache, const float* __restrict__ kscale_p,
                  const float* __restrict__ vscale_p, const int* __restrict__ btab,
                  const int* __restrict__ clen, float* __restrict__ out)
{
    const int split = blockIdx.x;
    const int h     = blockIdx.y;
    const int s     = blockIdx.z;
    const int ctx   = clen[s];
    const int c0    = split * CHUNK;
    const int nsp   = (ctx + CHUNK - 1) / CHUNK;   // active splits for this seq
    if (split >= nsp) return;
    const int nvalid = min(CHUNK, ctx - c0);
    const int ntile  = (nvalid + TILE - 1) / TILE;

    __shared__ unsigned short kt[TILE][ROWB];   // dequantized K tile (bf16)
    __shared__ float          vtf[TILE][ROWF];  // dequantized V tile (f32, bf16-exact)
    __shared__ float qs[GQ * HDIM];
    __shared__ float ps[GQ][TILE];              // per-warp softmax weights
    __shared__ int   s_last;

    const int t = threadIdx.x;
    const int w = t >> 5;     // warp = query head within GQA group
    const int l = t & 31;     // lane

    // stage Q (512 floats, raw f32 as in reference)
    ((float4*)qs)[t] = ((const float4*)(q + (size_t)s * (NHEAD * HDIM)
                                          + (size_t)h * (GQ * HDIM)))[t];
    const float ks = kscale_p[h];
    const float vs = vscale_p[h];

    // hoist the chunk's 8 cache-block indices (independent LDGs, once per CTA)
    int blkArr[CHUNK / BSZ];
    #pragma unroll
    for (int j = 0; j < CHUNK / BSZ; ++j)
        blkArr[j] = btab[s * MBLK + (c0 >> 4) + j];

    float  m    = NEG_BIG;
    float  lsum = 0.f;
    float4 o    = make_float4(0.f, 0.f, 0.f, 0.f);

    for (int tb = 0; tb < ntile; ++tb) {
        const int base = c0 + tb * TILE;

        // ---- stage + dequantize K/V tile: warp w loads rows (i*4 + w), 512B rows coalesced
        #pragma unroll
        for (int i = 0; i < 8; ++i) {
            const int pl = i * 4 + w;          // tile-local position 0..31
            const int P  = base + pl;          // global position (< 2048 always: safe loads)
            const long long blk  = (long long)blkArr[tb * 2 + (pl >> 4)];
            const long long roff = ((blk * BSZ + (P & 15)) * NKVH + h) * (long long)HDIM;
            float4 kv = ((const float4*)(kcache + roff))[l];
            float4 vv = ((const float4*)(vcache + roff))[l];
            if (P == ctx - 1) {  // new token: reference scatters fp8(x/scale) at this slot
                const float* kp = knew + (size_t)s * (NKVH * HDIM) + h * HDIM + l * 4;
                const float* vp = vnew + (size_t)s * (NKVH * HDIM) + h * HDIM + l * 4;
                kv.x = __fdiv_rn(kp[0], ks); kv.y = __fdiv_rn(kp[1], ks);
                kv.z = __fdiv_rn(kp[2], ks); kv.w = __fdiv_rn(kp[3], ks);
                vv.x = __fdiv_rn(vp[0], vs); vv.y = __fdiv_rn(vp[1], vs);
                vv.z = __fdiv_rn(vp[2], vs); vv.w = __fdiv_rn(vp[3], vs);
            }
            *(uint2*)&kt[pl][l * 4]   = dq4_bf(kv, ks);
            *(float4*)&vtf[pl][l * 4] = dq4_f32(vv, vs);
        }
        __syncthreads();

        // ---- scores: warp w = head w, lane l = position l (row l of K, 8 bf16 per LDS.128)
        float4 acc = make_float4(0.f, 0.f, 0.f, 0.f);
        #pragma unroll
        for (int d8 = 0; d8 < 16; ++d8) {
            const uint4  kq = *(const uint4*)&kt[l][d8 * 8];
            const float4 qa = *(const float4*)&qs[w * HDIM + d8 * 8];
            const float4 qb = *(const float4*)&qs[w * HDIM + d8 * 8 + 4];
            acc.x += bflo(kq.x) * qa.x; acc.y += bfhi(kq.x) * qa.y;
            acc.z += bflo(kq.y) * qa.z; acc.w += bfhi(kq.y) * qa.w;
            acc.x += bflo(kq.z) * qb.x; acc.y += bfhi(kq.z) * qb.y;
            acc.z += bflo(kq.w) * qb.z; acc.w += bfhi(kq.w) * qb.w;
        }
        float sc = ((acc.x + acc.y) + (acc.z + acc.w)) * ATTN_SCALE;
        if (base + l >= ctx) sc = NEG_BIG;

        // online softmax (per warp)
        float tm = sc;
        #pragma unroll
        for (int off = 16; off > 0; off >>= 1)
            tm = fmaxf(tm, __shfl_xor_sync(0xFFFFFFFFu, tm, off));
        const float mnew  = fmaxf(m, tm);
        const float alpha = __expf(m - mnew);
        const float p     = __expf(sc - mnew);   // masked lanes underflow to 0
        float tsum = p;
        #pragma unroll
        for (int off = 16; off > 0; off >>= 1)
            tsum += __shfl_xor_sync(0xFFFFFFFFu, tsum, off);
        lsum = lsum * alpha + tsum;
        m = mnew;

        // ---- publish weights to smem (per-warp row), read back as broadcast LDS.128
        __syncwarp();
        ps[w][l] = p;
        __syncwarp();

        // ---- accumulate O: lane l owns dims 4l..4l+3
        o.x *= alpha; o.y *= alpha; o.z *= alpha; o.w *= alpha;
        #pragma unroll
        for (int j = 0; j < 8; ++j) {
            const float4 pw = *(const float4*)&ps[w][j * 4];
            const float4 v0 = *(const float4*)&vtf[j * 4 + 0][l * 4];
            const float4 v1 = *(const float4*)&vtf[j * 4 + 1][l * 4];
            const float4 v2 = *(const float4*)&vtf[j * 4 + 2][l * 4];
            const float4 v3 = *(const float4*)&vtf[j * 4 + 3][l * 4];
            o.x += pw.x * v0.x; o.y += pw.x * v0.y; o.z += pw.x * v0.z; o.w += pw.x * v0.w;
            o.x += pw.y * v1.x; o.y += pw.y * v1.y; o.z += pw.y * v1.z; o.w += pw.y * v1.w;
            o.x += pw.z * v2.x; o.y += pw.z * v2.y; o.z += pw.z * v2.z; o.w += pw.z * v2.w;
            o.x += pw.w * v3.x; o.y += pw.w * v3.y; o.z += pw.w * v3.z; o.w += pw.w * v3.w;
        }
        __syncthreads();
    }

    // ---- publish partials
    *(float4*)&g_po[s][h][split][w][l * 4] = o;
    if (l == 0) { g_pm[s][h][split][w] = m; g_pl[s][h][split][w] = lsum; }
    __threadfence();
    __syncthreads();

    // ---- last-CTA-per-(s,h) detection (threadFenceReduction pattern)
    if (t == 0) {
        const int old = atomicAdd(&g_cnt[s][h], 1);
        int last = (old == nsp - 1);
        if (last) g_cnt[s][h] = 0;     // restore for next graph replay (deterministic)
        s_last = last;
    }
    __syncthreads();
    if (!s_last) return;
    __threadfence();

    // ---- in-place combine for this (s,h): warp w = GQA sub-head, L2-resident reads
    const float mi = (l < nsp) ? g_pm[s][h][l][w] : NEG_BIG;
    const float li = (l < nsp) ? g_pl[s][h][l][w] : 0.f;
    float M = mi;
    #pragma unroll
    for (int off = 16; off > 0; off >>= 1)
        M = fmaxf(M, __shfl_xor_sync(0xFFFFFFFFu, M, off));
    const float wi = __expf(mi - M);     // 0 for inactive lanes
    float L = wi * li;
    #pragma unroll
    for (int off = 16; off > 0; off >>= 1)
        L += __shfl_xor_sync(0xFFFFFFFFu, L, off);

    float4 acc = make_float4(0.f, 0.f, 0.f, 0.f);
    #pragma unroll
    for (int i = 0; i < NSPLIT; ++i) {
        if (i < nsp) {
            const float wgt = __shfl_sync(0xFFFFFFFFu, wi, i);
            const float4 pv = *(const float4*)&g_po[s][h][i][w][l * 4];
            acc.x += wgt * pv.x; acc.y += wgt * pv.y;
            acc.z += wgt * pv.z; acc.w += wgt * pv.w;
        }
    }
    const float inv = 1.f / L;
    float4 r = make_float4(acc.x * inv, acc.y * inv, acc.z * inv, acc.w * inv);
    *(float4*)(out + (size_t)s * (NHEAD * HDIM)
                   + (size_t)(h * GQ + w) * HDIM + l * 4) = r;
}

extern "C" void kernel_launch(void* const* d_in, const int* in_sizes, int n_in,
                              void* d_out, int out_size) {
    (void)in_sizes; (void)n_in; (void)out_size;
    const float* q    = (const float*)d_in[0];
    const float* k    = (const float*)d_in[1];
    const float* v    = (const float*)d_in[2];
    const float* kc   = (const float*)d_in[3];
    const float* vc   = (const float*)d_in[4];
    const float* ksc  = (const float*)d_in[5];
    const float* vsc  = (const float*)d_in[6];
    // d_in[7] slot_mapping: unused (position ctx-1 substitution is equivalent)
    const int*   btab = (const int*)d_in[8];   // JAX x64 disabled -> int32
    const int*   clen = (const int*)d_in[9];

    dim3 g1(NSPLIT, NKVH, S_N);
    attn_fused_kernel<<<g1, 128>>>(q, k, v, kc, vc, ksc, vsc, btab, clen, (float*)d_out);
}

// round 10
// speedup vs baseline: 1.1656x; 1.1656x over previous
#include <cuda_runtime.h>
#include <cuda_fp8.h>
#include <cuda_bf16.h>

#define S_N     32
#define NHEAD   32
#define HDIM    128
#define NKVH    8
#define GQ      4
#define BSZ     16
#define MBLK    128
#define NSPLIT  16
#define CHUNK   128
#define TILE    32
#define ROWB    136          // bf16 elems per conv smem row (272B = 16B-aligned, conflict-free)
#define ATTN_SCALE 0.08838834764831845f
#define NEG_BIG   -3.402823466e38f

// dynamic smem layout (bytes)
#define OFF_RAWK  0
#define OFF_RAWV  (TILE * HDIM * 4)                        // 16384
#define OFF_KT    (OFF_RAWV + TILE * HDIM * 4)             // 32768
#define OFF_VT    (OFF_KT + TILE * ROWB * 2)               // +8704
#define OFF_QS    (OFF_VT + TILE * ROWB * 2)               // +8704
#define OFF_LAST  (OFF_QS + GQ * HDIM * 4)                 // +2048
#define SMEM_BYTES (OFF_LAST + 16)                         // ~52.2 KB

// split-KV partial scratch (static device memory: allocation-free)
__device__ float g_po[S_N][NKVH][NSPLIT][GQ][HDIM];
__device__ float g_pm[S_N][NKVH][NSPLIT][GQ];
__device__ float g_pl[S_N][NKVH][NSPLIT][GQ];
__device__ int   g_cnt[S_N][NKVH];   // zero-init; protocol restores 0 every run

__device__ __forceinline__ void cp16(void* dst_smem, const void* src) {
    unsigned d = (unsigned)__cvta_generic_to_shared(dst_smem);
    asm volatile("cp.async.cg.shared.global [%0], [%1], 16;" :: "r"(d), "l"(src));
}
#define CP_COMMIT() asm volatile("cp.async.commit_group;" ::: "memory")
#define CP_WAIT0()  asm volatile("cp.async.wait_group 0;" ::: "memory")

// Exact emulation of reference dequant chain -> two packed bf16x2 words
__device__ __forceinline__ uint2 dq4_bf(float4 c, float s) {
    float2 a = make_float2(c.x, c.y);
    float2 b = make_float2(c.z, c.w);
    __nv_fp8x2_storage_t p0 = __nv_cvt_float2_to_fp8x2(a, __NV_SATFINITE, __NV_E4M3);
    __nv_fp8x2_storage_t p1 = __nv_cvt_float2_to_fp8x2(b, __NV_SATFINITE, __NV_E4M3);
    __half2_raw h0 = __nv_cvt_fp8x2_to_halfraw2(p0, __NV_E4M3);
    __half2_raw h1 = __nv_cvt_fp8x2_to_halfraw2(p1, __NV_E4M3);
    float2 f0 = __half22float2(*reinterpret_cast<__half2*>(&h0));
    float2 f1 = __half22float2(*reinterpret_cast<__half2*>(&h1));
    f0.x *= s; f0.y *= s; f1.x *= s; f1.y *= s;
    __nv_bfloat162 bb0 = __float22bfloat162_rn(f0);
    __nv_bfloat162 bb1 = __float22bfloat162_rn(f1);
    uint2 r;
    r.x = *reinterpret_cast<unsigned*>(&bb0);
    r.y = *reinterpret_cast<unsigned*>(&bb1);
    return r;
}

// bf16x2 word -> two exact f32 (bf16 value = upper 16 bits of f32)
__device__ __forceinline__ float bflo(unsigned u) { return __uint_as_float(u << 16); }
__device__ __forceinline__ float bfhi(unsigned u) { return __uint_as_float(u & 0xFFFF0000u); }

__global__ void __launch_bounds__(128)
attn_fused_kernel(const float* __restrict__ q, const float* __restrict__ knew,
                  const float* __restrict__ vnew, const float* __restrict__ kcache,
                  const float* __restrict__ vcache, const float* __restrict__ kscale_p,
                  const float* __restrict__ vscale_p, const int* __restrict__ btab,
                  const int* __restrict__ clen, float* __restrict__ out)
{
    extern __shared__ char smem[];
    float*          rawK = (float*)(smem + OFF_RAWK);          // [TILE][HDIM] f32
    float*          rawV = (float*)(smem + OFF_RAWV);
    unsigned short* kt   = (unsigned short*)(smem + OFF_KT);   // [TILE][ROWB] bf16
    unsigned short* vt   = (unsigned short*)(smem + OFF_VT);
    float*          qs   = (float*)(smem + OFF_QS);            // [GQ*HDIM]
    int*            s_last = (int*)(smem + OFF_LAST);

    const int split = blockIdx.x;
    const int h     = blockIdx.y;
    const int s     = blockIdx.z;
    const int ctx   = clen[s];
    const int c0    = split * CHUNK;
    const int nsp   = (ctx + CHUNK - 1) / CHUNK;   // active splits for this seq
    if (split >= nsp) return;
    const int nvalid = min(CHUNK, ctx - c0);
    const int ntile  = (nvalid + TILE - 1) / TILE;

    const int t = threadIdx.x;
    const int w = t >> 5;     // warp = query head within GQA group
    const int l = t & 31;     // lane

    // stage Q (512 floats, raw f32 as in reference)
    ((float4*)qs)[t] = ((const float4*)(q + (size_t)s * (NHEAD * HDIM)
                                          + (size_t)h * (GQ * HDIM)))[t];
    const float ks = kscale_p[h];
    const float vs = vscale_p[h];
    const float* kp = knew + (size_t)s * (NKVH * HDIM) + h * HDIM + l * 4;
    const float* vp = vnew + (size_t)s * (NKVH * HDIM) + h * HDIM + l * 4;

    // hoist the chunk's 8 cache-block indices (independent LDGs, once per CTA)
    int blkArr[CHUNK / BSZ];
    #pragma unroll
    for (int j = 0; j < CHUNK / BSZ; ++j)
        blkArr[j] = btab[s * MBLK + (c0 >> 4) + j];

    // issue one tile's raw K/V into smem via cp.async (no registers held)
    auto issue_tile = [&](int tb) {
        const int base = c0 + tb * TILE;
        #pragma unroll
        for (int i = 0; i < 8; ++i) {
            const int pl = i * 4 + w;          // tile-local position 0..31
            const int P  = base + pl;          // global position (< 2048 always: safe)
            const long long blk  = (long long)blkArr[tb * 2 + (pl >> 4)];
            const long long roff = ((blk * BSZ + (P & 15)) * NKVH + h) * (long long)HDIM;
            cp16(&rawK[pl * HDIM + l * 4], kcache + roff + l * 4);
            cp16(&rawV[pl * HDIM + l * 4], vcache + roff + l * 4);
        }
        CP_COMMIT();
    };

    // dq-convert raw f32 tile -> bf16 conv tile (with new-token substitution)
    auto convert_tile = [&](int tb) {
        const int base = c0 + tb * TILE;
        #pragma unroll
        for (int i = 0; i < 8; ++i) {
            const int pl = i * 4 + w;
            float4 kv = *(const float4*)&rawK[pl * HDIM + l * 4];
            float4 vv = *(const float4*)&rawV[pl * HDIM + l * 4];
            if (base + pl == ctx - 1) {  // new token: reference scatters fp8(x/scale) here
                float4 kn4 = *(const float4*)kp;
                float4 vn4 = *(const float4*)vp;
                kv = make_float4(__fdiv_rn(kn4.x, ks), __fdiv_rn(kn4.y, ks),
                                 __fdiv_rn(kn4.z, ks), __fdiv_rn(kn4.w, ks));
                vv = make_float4(__fdiv_rn(vn4.x, vs), __fdiv_rn(vn4.y, vs),
                                 __fdiv_rn(vn4.z, vs), __fdiv_rn(vn4.w, vs));
            }
            *(uint2*)&kt[pl * ROWB + l * 4] = dq4_bf(kv, ks);
            *(uint2*)&vt[pl * ROWB + l * 4] = dq4_bf(vv, vs);
        }
    };

    float  m    = NEG_BIG;
    float  lsum = 0.f;
    float4 o    = make_float4(0.f, 0.f, 0.f, 0.f);

    // prologue: stage tile 0
    issue_tile(0);
    CP_WAIT0();
    __syncthreads();
    convert_tile(0);
    __syncthreads();

    for (int tb = 0; tb < ntile; ++tb) {
        const int base = c0 + tb * TILE;
        const bool more = (tb + 1 < ntile);

        // overlap: next tile's gmem->smem copies fly while we compute this tile
        if (more) issue_tile(tb + 1);

        // ---- scores: warp w = head w, lane l = position l (row l of K, 8 bf16 per LDS.128)
        float4 acc = make_float4(0.f, 0.f, 0.f, 0.f);
        #pragma unroll
        for (int d8 = 0; d8 < 16; ++d8) {
            const uint4  kq = *(const uint4*)&kt[l * ROWB + d8 * 8];
            const float4 qa = *(const float4*)&qs[w * HDIM + d8 * 8];
            const float4 qb = *(const float4*)&qs[w * HDIM + d8 * 8 + 4];
            acc.x += bflo(kq.x) * qa.x; acc.y += bfhi(kq.x) * qa.y;
            acc.z += bflo(kq.y) * qa.z; acc.w += bfhi(kq.y) * qa.w;
            acc.x += bflo(kq.z) * qb.x; acc.y += bfhi(kq.z) * qb.y;
            acc.z += bflo(kq.w) * qb.z; acc.w += bfhi(kq.w) * qb.w;
        }
        float sc = ((acc.x + acc.y) + (acc.z + acc.w)) * ATTN_SCALE;
        if (base + l >= ctx) sc = NEG_BIG;

        // online softmax (per warp)
        float tm = sc;
        #pragma unroll
        for (int off = 16; off > 0; off >>= 1)
            tm = fmaxf(tm, __shfl_xor_sync(0xFFFFFFFFu, tm, off));
        const float mnew  = fmaxf(m, tm);
        const float alpha = __expf(m - mnew);
        const float p     = __expf(sc - mnew);   // masked lanes underflow to 0
        float tsum = p;
        #pragma unroll
        for (int off = 16; off > 0; off >>= 1)
            tsum += __shfl_xor_sync(0xFFFFFFFFu, tsum, off);
        lsum = lsum * alpha + tsum;
        m = mnew;

        // ---- accumulate O: lane l owns dims 4l..4l+3; weights broadcast by shuffle
        o.x *= alpha; o.y *= alpha; o.z *= alpha; o.w *= alpha;
        #pragma unroll
        for (int pp = 0; pp < 32; ++pp) {
            const float wgt = __shfl_sync(0xFFFFFFFFu, p, pp);
            const uint2 vq  = *(const uint2*)&vt[pp * ROWB + l * 4];
            o.x += wgt * bflo(vq.x); o.y += wgt * bfhi(vq.x);
            o.z += wgt * bflo(vq.y); o.w += wgt * bfhi(vq.y);
        }
        __syncthreads();   // all warps done reading kt/vt of tile tb

        if (more) {
            CP_WAIT0();        // this thread's copies landed
            __syncthreads();   // everyone's copies landed
            convert_tile(tb + 1);
            __syncthreads();   // conv tile tb+1 ready
        }
    }

    // ---- publish partials
    *(float4*)&g_po[s][h][split][w][l * 4] = o;
    if (l == 0) { g_pm[s][h][split][w] = m; g_pl[s][h][split][w] = lsum; }
    __threadfence();
    __syncthreads();

    // ---- last-CTA-per-(s,h) detection (threadFenceReduction pattern)
    if (t == 0) {
        const int old = atomicAdd(&g_cnt[s][h], 1);
        int last = (old == nsp - 1);
        if (last) g_cnt[s][h] = 0;     // restore for next graph replay (deterministic)
        *s_last = last;
    }
    __syncthreads();
    if (!*s_last) return;
    __threadfence();

    // ---- in-place combine for this (s,h): warp w = GQA sub-head, L2-resident reads
    const float mi = (l < nsp) ? g_pm[s][h][l][w] : NEG_BIG;
    const float li = (l < nsp) ? g_pl[s][h][l][w] : 0.f;
    float M = mi;
    #pragma unroll
    for (int off = 16; off > 0; off >>= 1)
        M = fmaxf(M, __shfl_xor_sync(0xFFFFFFFFu, M, off));
    const float wi = __expf(mi - M);     // 0 for inactive lanes
    float L = wi * li;
    #pragma unroll
    for (int off = 16; off > 0; off >>= 1)
        L += __shfl_xor_sync(0xFFFFFFFFu, L, off);

    float4 acc = make_float4(0.f, 0.f, 0.f, 0.f);
    #pragma unroll
    for (int i = 0; i < NSPLIT; ++i) {
        if (i < nsp) {
            const float wgt = __shfl_sync(0xFFFFFFFFu, wi, i);
            const float4 pv = *(const float4*)&g_po[s][h][i][w][l * 4];
            acc.x += wgt * pv.x; acc.y += wgt * pv.y;
            acc.z += wgt * pv.z; acc.w += wgt * pv.w;
        }
    }
    const float inv = 1.f / L;
    float4 r = make_float4(acc.x * inv, acc.y * inv, acc.z * inv, acc.w * inv);
    *(float4*)(out + (size_t)s * (NHEAD * HDIM)
                   + (size_t)(h * GQ + w) * HDIM + l * 4) = r;
}

extern "C" void kernel_launch(void* const* d_in, const int* in_sizes, int n_in,
                              void* d_out, int out_size) {
    (void)in_sizes; (void)n_in; (void)out_size;
    const float* q    = (const float*)d_in[0];
    const float* k    = (const float*)d_in[1];
    const float* v    = (const float*)d_in[2];
    const float* kc   = (const float*)d_in[3];
    const float* vc   = (const float*)d_in[4];
    const float* ksc  = (const float*)d_in[5];
    const float* vsc  = (const float*)d_in[6];
    // d_in[7] slot_mapping: unused (position ctx-1 substitution is equivalent)
    const int*   btab = (const int*)d_in[8];   // JAX x64 disabled -> int32
    const int*   clen = (const int*)d_in[9];

    cudaFuncSetAttribute(attn_fused_kernel,
                         cudaFuncAttributeMaxDynamicSharedMemorySize, SMEM_BYTES);
    dim3 g1(NSPLIT, NKVH, S_N);
    attn_fused_kernel<<<g1, 128, SMEM_BYTES>>>(q, k, v, kc, vc, ksc, vsc,
                                               btab, clen, (float*)d_out);
}